// round 1
// baseline (speedup 1.0000x reference)
#include <cuda_runtime.h>
#include <math.h>

#define Bq 2
#define Nq 2048
#define Fq 128
#define Mq 8
#define Uq 64
#define TI 8      // i rows per block in main kernel
#define JC 64     // j chunk

// Scratch (allocation-free rule: __device__ globals)
__device__ float g_beta[Bq * Nq * Uq];            // (B,N,U)      1 MB
__device__ float g_alpha[Bq * Nq * Mq * Uq];      // (B,N,M,U)    8 MB

// Packed fp32x2 FMA (sm_100+): acc.lo += a.lo*b.lo ; acc.hi += a.hi*b.hi
#define FFMA2(acc, a, bb) asm("fma.rn.f32x2 %0, %1, %2, %0;" : "+l"(acc) : "l"(a), "l"(bb))

// ---------------------------------------------------------------------------
// Kernel A: beta = seq @ e_w  (cols 0..63 of virtual W),
//           alpha = seq @ v_w (cols 64..575).
// GEMM (4096 x 128) @ (128 x 576). Block: 128 rows x 64 cols, 256 threads,
// thread tile 8x4, k-chunks of 32.
// ---------------------------------------------------------------------------
__global__ void __launch_bounds__(256) precompute_kernel(
        const float* __restrict__ seq,
        const float* __restrict__ e_w,
        const float* __restrict__ v_w) {
    __shared__ float sS[128][33];   // 128 rows x 32 k (+pad)
    __shared__ float sW[32][68];    // 32 k x 64 cols (+pad)

    const int bx = blockIdx.x;              // 0..8 : column block
    const int by = blockIdx.y;              // 0..31: row block
    const int row0 = by * 128;

    const float* wsrc;
    int wstride, c0;
    if (bx == 0) { wsrc = e_w; wstride = Uq;      c0 = 0; }
    else         { wsrc = v_w; wstride = Mq * Uq; c0 = (bx - 1) * 64; }

    const int tid = threadIdx.x;
    const int tx = tid & 15;      // 16 col groups x 4 cols
    const int ty = tid >> 4;      // 16 row groups x 8 rows

    float acc[8][4];
#pragma unroll
    for (int r = 0; r < 8; r++)
#pragma unroll
        for (int c = 0; c < 4; c++) acc[r][c] = 0.f;

    for (int fb = 0; fb < Fq; fb += 32) {
        // stage seq tile: 128 x 32 floats
        for (int v = tid; v < 128 * 8; v += 256) {
            int r = v >> 3, fq = (v & 7) * 4;
            float4 t = *(const float4*)&seq[(row0 + r) * Fq + fb + fq];
            sS[r][fq + 0] = t.x; sS[r][fq + 1] = t.y;
            sS[r][fq + 2] = t.z; sS[r][fq + 3] = t.w;
        }
        // stage W tile: 32 x 64 floats
        for (int v = tid; v < 32 * 16; v += 256) {
            int f = v >> 4, cq = (v & 15) * 4;
            float4 t = *(const float4*)&wsrc[(fb + f) * wstride + c0 + cq];
            *(float4*)&sW[f][cq] = t;
        }
        __syncthreads();

#pragma unroll 4
        for (int f = 0; f < 32; f++) {
            float a[8];
#pragma unroll
            for (int r = 0; r < 8; r++) a[r] = sS[ty * 8 + r][f];
            float4 b4 = *(const float4*)&sW[f][tx * 4];
            float bb[4] = {b4.x, b4.y, b4.z, b4.w};
#pragma unroll
            for (int r = 0; r < 8; r++)
#pragma unroll
                for (int c = 0; c < 4; c++)
                    acc[r][c] = fmaf(a[r], bb[c], acc[r][c]);
        }
        __syncthreads();
    }

#pragma unroll
    for (int r = 0; r < 8; r++) {
        const int bn = row0 + ty * 8 + r;
#pragma unroll
        for (int c = 0; c < 4; c++) {
            const int col = tx * 4 + c;
            if (bx == 0) g_beta[bn * Uq + col] = acc[r][c];
            else         g_alpha[bn * (Mq * Uq) + c0 + col] = acc[r][c];
        }
    }
}

// ---------------------------------------------------------------------------
// Kernel B: out[b,i,m,u] = sigmoid( sum_j graph[b,i,j,m]*beta[b,j,u] + alpha )
// One block per (b, 8 consecutive i). 256 threads:
//   tid bits: ug = tid&7 (8 u-groups of 8u), mg = (tid>>3)&3 (4 m-groups of 2m),
//             ig = tid>>5 (8 i). Thread tile: 1i x 2m x 8u = 8 packed f32x2 acc.
// Graph chunk stored value-DUPLICATED in smem so each graph scalar is already
// a (g,g) b64 lane pair -> FFMA2 needs no splat movs.
// ---------------------------------------------------------------------------
__global__ void __launch_bounds__(256) multigraph_main_kernel(
        const float* __restrict__ graph,
        float* __restrict__ out) {
    __shared__ float sG[TI * JC * Mq * 2];   // 32 KB, ((i*JC+j)*M + m)*2 + dup
    __shared__ float sBeta[JC * Uq];         // 16 KB

    const int blk = blockIdx.x;              // 0..511
    const int b   = blk >> 8;                // 256 i-blocks per batch
    const int i0  = (blk & 255) * TI;

    const int tid = threadIdx.x;
    const int ug = tid & 7;
    const int mg = (tid >> 3) & 3;
    const int ig = tid >> 5;
    const int ub = ug * 8;
    const int m0 = mg * 2;

    unsigned long long acc[8];
#pragma unroll
    for (int k = 0; k < 8; k++) acc[k] = 0ull;  // (0.f, 0.f)

    const float* gbase = graph + (long long)(b * Nq + i0) * Nq * Mq;
    const float* bbase = g_beta + b * Nq * Uq;

    for (int j0 = 0; j0 < Nq; j0 += JC) {
        // stage graph chunk: TI*JC*M = 4096 floats (1024 float4), duplicated
        for (int v = tid; v < 1024; v += 256) {
            int i   = v >> 7;            // 128 float4 per i-row
            int rem = v & 127;
            int j   = rem >> 1;
            int mh  = (rem & 1) * 4;
            float4 t = *(const float4*)&gbase[((long long)i * Nq + j0 + j) * Mq + mh];
            float* d = &sG[((i * JC + j) * Mq + mh) * 2];
            d[0] = t.x; d[1] = t.x; d[2] = t.y; d[3] = t.y;
            d[4] = t.z; d[5] = t.z; d[6] = t.w; d[7] = t.w;
        }
        // stage beta chunk: JC*U = 4096 floats
        for (int v = tid; v < 1024; v += 256) {
            int j  = v >> 4;
            int uq = (v & 15) * 4;
            *(float4*)&sBeta[j * Uq + uq] =
                *(const float4*)&bbase[(j0 + j) * Uq + uq];
        }
        __syncthreads();

        const float* gp = &sG[((ig * JC) * Mq + m0) * 2];
        const float* bp = &sBeta[ub];

#pragma unroll 4
        for (int j = 0; j < JC; j++) {
            // (g_m0,g_m0) and (g_m0+1,g_m0+1) as two b64 lanes
            ulonglong2 g  = *(const ulonglong2*)(gp + j * (Mq * 2));
            // 8 u values = 4 packed pairs
            ulonglong2 p01 = *(const ulonglong2*)(bp + j * Uq);
            ulonglong2 p23 = *(const ulonglong2*)(bp + j * Uq + 4);
            FFMA2(acc[0], g.x, p01.x);
            FFMA2(acc[1], g.x, p01.y);
            FFMA2(acc[2], g.x, p23.x);
            FFMA2(acc[3], g.x, p23.y);
            FFMA2(acc[4], g.y, p01.x);
            FFMA2(acc[5], g.y, p01.y);
            FFMA2(acc[6], g.y, p23.x);
            FFMA2(acc[7], g.y, p23.y);
        }
        __syncthreads();
    }

    // epilogue: + alpha, sigmoid, store
    const long long row = (long long)(b * Nq + i0 + ig);
#pragma unroll
    for (int k = 0; k < 8; k++) {
        const int m = m0 + (k >> 2);
        const int u = ub + (k & 3) * 2;
        const long long idx = (row * Mq + m) * Uq + u;
        float lo = __uint_as_float((unsigned)(acc[k] & 0xffffffffull));
        float hi = __uint_as_float((unsigned)(acc[k] >> 32));
        float x0 = lo + g_alpha[idx];
        float x1 = hi + g_alpha[idx + 1];
        float2 o;
        o.x = 1.0f / (1.0f + __expf(-x0));
        o.y = 1.0f / (1.0f + __expf(-x1));
        *(float2*)&out[idx] = o;
    }
}

// ---------------------------------------------------------------------------
extern "C" void kernel_launch(void* const* d_in, const int* in_sizes, int n_in,
                              void* d_out, int out_size) {
    const float* seq   = (const float*)d_in[0];   // (B,N,F)
    const float* graph = (const float*)d_in[1];   // (B,N,N,M)
    const float* e_w   = (const float*)d_in[2];   // (F,U)
    const float* v_w   = (const float*)d_in[3];   // (F,M,U)
    float* out = (float*)d_out;                   // (B,N,M,U)

    dim3 gridA(9, 32);
    precompute_kernel<<<gridA, 256>>>(seq, e_w, v_w);

    multigraph_main_kernel<<<512, 256>>>(graph, out);
    (void)in_sizes; (void)n_in; (void)out_size;
}

// round 2
// speedup vs baseline: 2.5007x; 2.5007x over previous
#include <cuda_runtime.h>
#include <math.h>

#define Bq 2
#define Nq 2048
#define Fq 128
#define Mq 8
#define Uq 64
#define TIq 16     // i rows per block (main kernel)
#define JC 32      // j chunk

// Scratch (allocation-free rule: __device__ globals)
__device__ float g_beta[Bq * Nq * Uq];            // (B,N,U)      1 MB
__device__ float g_alpha[Bq * Nq * Mq * Uq];      // (B,N,M,U)    8 MB

// Packed fp32x2 FMA (sm_100+): acc.lo += a.lo*b.lo ; acc.hi += a.hi*b.hi
#define FFMA2(acc, a, bb) asm("fma.rn.f32x2 %0, %1, %2, %0;" : "+l"(acc) : "l"(a), "l"(bb))

__device__ __forceinline__ unsigned long long splat2(float x) {
    unsigned long long r;
    asm("mov.b64 %0, {%1, %1};" : "=l"(r) : "r"(__float_as_uint(x)));
    return r;
}

// ---------------------------------------------------------------------------
// Kernel A: beta = seq @ e_w, alpha = seq @ v_w.
// GEMM (4096 x 128) @ (128 x 576). Unchanged from round 1 (passed, ~25us).
// ---------------------------------------------------------------------------
__global__ void __launch_bounds__(256) precompute_kernel(
        const float* __restrict__ seq,
        const float* __restrict__ e_w,
        const float* __restrict__ v_w) {
    __shared__ float sS[128][33];
    __shared__ float sW[32][68];

    const int bx = blockIdx.x;
    const int by = blockIdx.y;
    const int row0 = by * 128;

    const float* wsrc;
    int wstride, c0;
    if (bx == 0) { wsrc = e_w; wstride = Uq;      c0 = 0; }
    else         { wsrc = v_w; wstride = Mq * Uq; c0 = (bx - 1) * 64; }

    const int tid = threadIdx.x;
    const int tx = tid & 15;
    const int ty = tid >> 4;

    float acc[8][4];
#pragma unroll
    for (int r = 0; r < 8; r++)
#pragma unroll
        for (int c = 0; c < 4; c++) acc[r][c] = 0.f;

    for (int fb = 0; fb < Fq; fb += 32) {
        for (int v = tid; v < 128 * 8; v += 256) {
            int r = v >> 3, fq = (v & 7) * 4;
            float4 t = *(const float4*)&seq[(row0 + r) * Fq + fb + fq];
            sS[r][fq + 0] = t.x; sS[r][fq + 1] = t.y;
            sS[r][fq + 2] = t.z; sS[r][fq + 3] = t.w;
        }
        for (int v = tid; v < 32 * 16; v += 256) {
            int f = v >> 4, cq = (v & 15) * 4;
            float4 t = *(const float4*)&wsrc[(fb + f) * wstride + c0 + cq];
            *(float4*)&sW[f][cq] = t;
        }
        __syncthreads();

#pragma unroll 4
        for (int f = 0; f < 32; f++) {
            float a[8];
#pragma unroll
            for (int r = 0; r < 8; r++) a[r] = sS[ty * 8 + r][f];
            float4 b4 = *(const float4*)&sW[f][tx * 4];
            float bb[4] = {b4.x, b4.y, b4.z, b4.w};
#pragma unroll
            for (int r = 0; r < 8; r++)
#pragma unroll
                for (int c = 0; c < 4; c++)
                    acc[r][c] = fmaf(a[r], bb[c], acc[r][c]);
        }
        __syncthreads();
    }

#pragma unroll
    for (int r = 0; r < 8; r++) {
        const int bn = row0 + ty * 8 + r;
#pragma unroll
        for (int c = 0; c < 4; c++) {
            const int col = tx * 4 + c;
            if (bx == 0) g_beta[bn * Uq + col] = acc[r][c];
            else         g_alpha[bn * (Mq * Uq) + c0 + col] = acc[r][c];
        }
    }
}

// ---------------------------------------------------------------------------
// Kernel B: out[b,i,m,u] = sigmoid( sum_j graph[b,i,j,m]*beta[b,j,u] + alpha )
// 256 blocks x 128 threads. Block tile: 16 i x 8 m x 64 u.
// Thread tile: 2i x 4m x 8u = 32 packed (m-pair) f32x2 accumulators.
//   tid bits: ug = tid&7 (u group of 8), mg = (tid>>3)&1 (m half), ig = tid>>4.
// Graph float2 (m0,m1) from smem is the packed FFMA2 operand (no movs);
// beta scalars are splatted in registers (fills spare issue slots).
// Per thread-j: 64B smem for 64 FMA  (round 1 was 48B for 16 FMA).
// ---------------------------------------------------------------------------
#define SG_STRIDE 260        // floats per i row (256 + 4 pad -> kills ig bank alias)
#define SB_STRIDE 72         // floats per j row (64 + swizzle room + pad)

__global__ void __launch_bounds__(128, 4) multigraph_main_kernel(
        const float* __restrict__ graph,
        float* __restrict__ out) {
    __shared__ float sG[TIq * SG_STRIDE];   // [i][j*8+m] (+pad)   16.6 KB
    __shared__ float sB[JC * SB_STRIDE];    // [j][u swizzled]      9.2 KB

    const int blk = blockIdx.x;             // 0..255
    const int b   = blk >> 7;
    const int i0  = (blk & 127) * TIq;

    const int tid = threadIdx.x;
    const int ug = tid & 7;
    const int mg = (tid >> 3) & 1;
    const int ig = tid >> 4;                // 0..7
    const int ub  = ug * 8;                 // output u base
    const int ubs = ub + (ug >= 4 ? 4 : 0); // swizzled smem u base

    unsigned long long acc[32];             // [ii][mp][u] = [2][2][8]
#pragma unroll
    for (int k = 0; k < 32; k++) acc[k] = 0ull;

    const float* gbase = graph + (long long)(b * Nq + i0) * Nq * Mq;
    const float* bbase = g_beta + b * Nq * Uq;

    for (int j0 = 0; j0 < Nq; j0 += JC) {
        // stage graph tile: 16i x 32j x 8m = 1024 float4 (layout matches global)
#pragma unroll
        for (int k = 0; k < 8; k++) {
            int v = tid + k * 128;
            int i = v >> 6, rem = v & 63;
            float4 t = *(const float4*)&gbase[(long long)i * Nq * Mq + j0 * Mq + rem * 4];
            *(float4*)&sG[i * SG_STRIDE + rem * 4] = t;
        }
        // stage beta tile: 32j x 64u = 512 float4, u-swizzled (+4 for u>=32)
#pragma unroll
        for (int k = 0; k < 4; k++) {
            int v = tid + k * 128;
            int j = v >> 4, uq = (v & 15) * 4;
            int uqs = uq + (uq >= 32 ? 4 : 0);
            *(float4*)&sB[j * SB_STRIDE + uqs] =
                *(const float4*)&bbase[(j0 + j) * Uq + uq];
        }
        __syncthreads();

#pragma unroll 2
        for (int j = 0; j < JC; j++) {
            const float* bp = &sB[j * SB_STRIDE + ubs];
            float4 b0 = *(const float4*)bp;
            float4 b1 = *(const float4*)(bp + 4);
            unsigned long long bs[8];
            bs[0] = splat2(b0.x); bs[1] = splat2(b0.y);
            bs[2] = splat2(b0.z); bs[3] = splat2(b0.w);
            bs[4] = splat2(b1.x); bs[5] = splat2(b1.y);
            bs[6] = splat2(b1.z); bs[7] = splat2(b1.w);
#pragma unroll
            for (int ii = 0; ii < 2; ii++) {
                ulonglong2 g = *(const ulonglong2*)
                    &sG[(ig * 2 + ii) * SG_STRIDE + j * 8 + mg * 4];
#pragma unroll
                for (int u = 0; u < 8; u++) FFMA2(acc[ii * 16 + u], g.x, bs[u]);
#pragma unroll
                for (int u = 0; u < 8; u++) FFMA2(acc[ii * 16 + 8 + u], g.y, bs[u]);
            }
        }
        __syncthreads();
    }

    // epilogue: + alpha, sigmoid, store (once per block)
#pragma unroll
    for (int ii = 0; ii < 2; ii++) {
        const long long row = (long long)(b * Nq) + i0 + ig * 2 + ii;
#pragma unroll
        for (int mp = 0; mp < 2; mp++) {
            const int m = mg * 4 + mp * 2;        // acc lo -> m, hi -> m+1
            const long long base = (row * Mq + m) * Uq + ub;
            const unsigned long long* a = &acc[ii * 16 + mp * 8];
#pragma unroll
            for (int q = 0; q < 2; q++) {
                float4 a0 = *(const float4*)&g_alpha[base + q * 4];
                float4 a1 = *(const float4*)&g_alpha[base + Uq + q * 4];
                float lo[4], hi[4];
#pragma unroll
                for (int t = 0; t < 4; t++) {
                    unsigned long long v = a[q * 4 + t];
                    lo[t] = __uint_as_float((unsigned)(v & 0xffffffffull));
                    hi[t] = __uint_as_float((unsigned)(v >> 32));
                }
                float4 o0, o1;
                o0.x = 1.0f / (1.0f + __expf(-(lo[0] + a0.x)));
                o0.y = 1.0f / (1.0f + __expf(-(lo[1] + a0.y)));
                o0.z = 1.0f / (1.0f + __expf(-(lo[2] + a0.z)));
                o0.w = 1.0f / (1.0f + __expf(-(lo[3] + a0.w)));
                o1.x = 1.0f / (1.0f + __expf(-(hi[0] + a1.x)));
                o1.y = 1.0f / (1.0f + __expf(-(hi[1] + a1.y)));
                o1.z = 1.0f / (1.0f + __expf(-(hi[2] + a1.z)));
                o1.w = 1.0f / (1.0f + __expf(-(hi[3] + a1.w)));
                *(float4*)&out[base + q * 4] = o0;
                *(float4*)&out[base + Uq + q * 4] = o1;
            }
        }
    }
}

// ---------------------------------------------------------------------------
extern "C" void kernel_launch(void* const* d_in, const int* in_sizes, int n_in,
                              void* d_out, int out_size) {
    const float* seq   = (const float*)d_in[0];   // (B,N,F)
    const float* graph = (const float*)d_in[1];   // (B,N,N,M)
    const float* e_w   = (const float*)d_in[2];   // (F,U)
    const float* v_w   = (const float*)d_in[3];   // (F,M,U)
    float* out = (float*)d_out;                   // (B,N,M,U)

    dim3 gridA(9, 32);
    precompute_kernel<<<gridA, 256>>>(seq, e_w, v_w);

    multigraph_main_kernel<<<256, 128>>>(graph, out);
    (void)in_sizes; (void)n_in; (void)out_size;
}

// round 3
// speedup vs baseline: 3.1430x; 1.2569x over previous
#include <cuda_runtime.h>
#include <math.h>

#define Bq 2
#define Nq 2048
#define Fq 128
#define Mq 8
#define Uq 64
#define TIq 16     // i rows per block (main kernel)
#define JC 32      // j chunk
#define JSPLIT 4   // split-K factor over j
#define JLEN (Nq / JSPLIT)
#define OUTSZ (Bq * Nq * Mq * Uq)

// Scratch (allocation-free rule: __device__ globals)
__device__ float g_beta[Bq * Nq * Uq];            // (B,N,U)        1 MB
__device__ float g_alpha[OUTSZ];                  // (B,N,M,U)      8 MB
__device__ float g_part[JSPLIT * OUTSZ];          // split-K partials 32 MB

// Packed fp32x2 FMA (sm_100+): acc.lo += a.lo*b.lo ; acc.hi += a.hi*b.hi
#define FFMA2(acc, a, bb) asm("fma.rn.f32x2 %0, %1, %2, %0;" : "+l"(acc) : "l"(a), "l"(bb))

__device__ __forceinline__ unsigned long long splat2(float x) {
    unsigned long long r;
    asm("mov.b64 %0, {%1, %1};" : "=l"(r) : "r"(__float_as_uint(x)));
    return r;
}

// ---------------------------------------------------------------------------
// Kernel A: beta = seq @ e_w, alpha = seq @ v_w.  (unchanged, ~25us)
// ---------------------------------------------------------------------------
__global__ void __launch_bounds__(256) precompute_kernel(
        const float* __restrict__ seq,
        const float* __restrict__ e_w,
        const float* __restrict__ v_w) {
    __shared__ float sS[128][33];
    __shared__ float sW[32][68];

    const int bx = blockIdx.x;
    const int by = blockIdx.y;
    const int row0 = by * 128;

    const float* wsrc;
    int wstride, c0;
    if (bx == 0) { wsrc = e_w; wstride = Uq;      c0 = 0; }
    else         { wsrc = v_w; wstride = Mq * Uq; c0 = (bx - 1) * 64; }

    const int tid = threadIdx.x;
    const int tx = tid & 15;
    const int ty = tid >> 4;

    float acc[8][4];
#pragma unroll
    for (int r = 0; r < 8; r++)
#pragma unroll
        for (int c = 0; c < 4; c++) acc[r][c] = 0.f;

    for (int fb = 0; fb < Fq; fb += 32) {
        for (int v = tid; v < 128 * 8; v += 256) {
            int r = v >> 3, fq = (v & 7) * 4;
            float4 t = *(const float4*)&seq[(row0 + r) * Fq + fb + fq];
            sS[r][fq + 0] = t.x; sS[r][fq + 1] = t.y;
            sS[r][fq + 2] = t.z; sS[r][fq + 3] = t.w;
        }
        for (int v = tid; v < 32 * 16; v += 256) {
            int f = v >> 4, cq = (v & 15) * 4;
            float4 t = *(const float4*)&wsrc[(fb + f) * wstride + c0 + cq];
            *(float4*)&sW[f][cq] = t;
        }
        __syncthreads();

#pragma unroll 4
        for (int f = 0; f < 32; f++) {
            float a[8];
#pragma unroll
            for (int r = 0; r < 8; r++) a[r] = sS[ty * 8 + r][f];
            float4 b4 = *(const float4*)&sW[f][tx * 4];
            float bb[4] = {b4.x, b4.y, b4.z, b4.w};
#pragma unroll
            for (int r = 0; r < 8; r++)
#pragma unroll
                for (int c = 0; c < 4; c++)
                    acc[r][c] = fmaf(a[r], bb[c], acc[r][c]);
        }
        __syncthreads();
    }

#pragma unroll
    for (int r = 0; r < 8; r++) {
        const int bn = row0 + ty * 8 + r;
#pragma unroll
        for (int c = 0; c < 4; c++) {
            const int col = tx * 4 + c;
            if (bx == 0) g_beta[bn * Uq + col] = acc[r][c];
            else         g_alpha[bn * (Mq * Uq) + c0 + col] = acc[r][c];
        }
    }
}

// ---------------------------------------------------------------------------
// Kernel B: split-K partials of sum_j graph[b,i,j,m]*beta[b,j,u].
// Grid (256, JSPLIT) x 128 threads. Block tile: 16 i x 8 m x 64 u x 512 j.
// Thread tile: 2i x 4m x 8u = 32 packed (m-pair) f32x2 accumulators.
// ---------------------------------------------------------------------------
#define SG_STRIDE 260        // floats per i row (256 + 4 pad)
#define SB_STRIDE 72         // floats per j row (64 + swizzle + pad)

__global__ void __launch_bounds__(128, 4) multigraph_main_kernel(
        const float* __restrict__ graph) {
    __shared__ float sG[TIq * SG_STRIDE];   // 16.6 KB
    __shared__ float sB[JC * SB_STRIDE];    //  9.2 KB

    const int blk = blockIdx.x;             // 0..255
    const int js  = blockIdx.y;             // 0..JSPLIT-1
    const int b   = blk >> 7;
    const int i0  = (blk & 127) * TIq;
    const int jbase = js * JLEN;

    const int tid = threadIdx.x;
    const int ug = tid & 7;
    const int mg = (tid >> 3) & 1;
    const int ig = tid >> 4;                // 0..7
    const int ub  = ug * 8;
    const int ubs = ub + (ug >= 4 ? 4 : 0);

    unsigned long long acc[32];             // [ii][mp][u] = [2][2][8]
#pragma unroll
    for (int k = 0; k < 32; k++) acc[k] = 0ull;

    const float* gbase = graph + (long long)(b * Nq + i0) * Nq * Mq;
    const float* bbase = g_beta + b * Nq * Uq;

    for (int jc = 0; jc < JLEN; jc += JC) {
        const int j0 = jbase + jc;
        // stage graph tile: 16i x 32j x 8m = 1024 float4
#pragma unroll
        for (int k = 0; k < 8; k++) {
            int v = tid + k * 128;
            int i = v >> 6, rem = v & 63;
            float4 t = *(const float4*)&gbase[(long long)i * Nq * Mq + j0 * Mq + rem * 4];
            *(float4*)&sG[i * SG_STRIDE + rem * 4] = t;
        }
        // stage beta tile: 32j x 64u, u-swizzled (+4 for u>=32)
#pragma unroll
        for (int k = 0; k < 4; k++) {
            int v = tid + k * 128;
            int j = v >> 4, uq = (v & 15) * 4;
            int uqs = uq + (uq >= 32 ? 4 : 0);
            *(float4*)&sB[j * SB_STRIDE + uqs] =
                *(const float4*)&bbase[(j0 + j) * Uq + uq];
        }
        __syncthreads();

#pragma unroll 2
        for (int j = 0; j < JC; j++) {
            const float* bp = &sB[j * SB_STRIDE + ubs];
            float4 b0 = *(const float4*)bp;
            float4 b1 = *(const float4*)(bp + 4);
            unsigned long long bs[8];
            bs[0] = splat2(b0.x); bs[1] = splat2(b0.y);
            bs[2] = splat2(b0.z); bs[3] = splat2(b0.w);
            bs[4] = splat2(b1.x); bs[5] = splat2(b1.y);
            bs[6] = splat2(b1.z); bs[7] = splat2(b1.w);
#pragma unroll
            for (int ii = 0; ii < 2; ii++) {
                ulonglong2 g = *(const ulonglong2*)
                    &sG[(ig * 2 + ii) * SG_STRIDE + j * 8 + mg * 4];
#pragma unroll
                for (int u = 0; u < 8; u++) FFMA2(acc[ii * 16 + u], g.x, bs[u]);
#pragma unroll
                for (int u = 0; u < 8; u++) FFMA2(acc[ii * 16 + 8 + u], g.y, bs[u]);
            }
        }
        __syncthreads();
    }

    // write partials (raw sums) to g_part[js]
    float* part = g_part + (long long)js * OUTSZ;
#pragma unroll
    for (int ii = 0; ii < 2; ii++) {
        const long long row = (long long)(b * Nq) + i0 + ig * 2 + ii;
#pragma unroll
        for (int mp = 0; mp < 2; mp++) {
            const int m = mg * 4 + mp * 2;
            const long long base = (row * Mq + m) * Uq + ub;
            const unsigned long long* a = &acc[ii * 16 + mp * 8];
#pragma unroll
            for (int q = 0; q < 2; q++) {
                float4 lo4, hi4;
                lo4.x = __uint_as_float((unsigned)(a[q * 4 + 0] & 0xffffffffull));
                lo4.y = __uint_as_float((unsigned)(a[q * 4 + 1] & 0xffffffffull));
                lo4.z = __uint_as_float((unsigned)(a[q * 4 + 2] & 0xffffffffull));
                lo4.w = __uint_as_float((unsigned)(a[q * 4 + 3] & 0xffffffffull));
                hi4.x = __uint_as_float((unsigned)(a[q * 4 + 0] >> 32));
                hi4.y = __uint_as_float((unsigned)(a[q * 4 + 1] >> 32));
                hi4.z = __uint_as_float((unsigned)(a[q * 4 + 2] >> 32));
                hi4.w = __uint_as_float((unsigned)(a[q * 4 + 3] >> 32));
                *(float4*)&part[base + q * 4] = lo4;
                *(float4*)&part[base + Uq + q * 4] = hi4;
            }
        }
    }
}

// ---------------------------------------------------------------------------
// Kernel C: out = sigmoid(sum_s part[s] + alpha).  HBM-bound, ~6us.
// ---------------------------------------------------------------------------
__global__ void __launch_bounds__(256) combine_kernel(float* __restrict__ out) {
    const long long v = (long long)blockIdx.x * 256 + threadIdx.x; // float4 index
    const long long idx = v * 4;
    float4 s = *(const float4*)&g_alpha[idx];
#pragma unroll
    for (int p = 0; p < JSPLIT; p++) {
        float4 t = *(const float4*)&g_part[(long long)p * OUTSZ + idx];
        s.x += t.x; s.y += t.y; s.z += t.z; s.w += t.w;
    }
    float4 o;
    o.x = 1.0f / (1.0f + __expf(-s.x));
    o.y = 1.0f / (1.0f + __expf(-s.y));
    o.z = 1.0f / (1.0f + __expf(-s.z));
    o.w = 1.0f / (1.0f + __expf(-s.w));
    *(float4*)&out[idx] = o;
}

// ---------------------------------------------------------------------------
extern "C" void kernel_launch(void* const* d_in, const int* in_sizes, int n_in,
                              void* d_out, int out_size) {
    const float* seq   = (const float*)d_in[0];   // (B,N,F)
    const float* graph = (const float*)d_in[1];   // (B,N,N,M)
    const float* e_w   = (const float*)d_in[2];   // (F,U)
    const float* v_w   = (const float*)d_in[3];   // (F,M,U)
    float* out = (float*)d_out;                   // (B,N,M,U)

    dim3 gridA(9, 32);
    precompute_kernel<<<gridA, 256>>>(seq, e_w, v_w);

    dim3 gridB(256, JSPLIT);
    multigraph_main_kernel<<<gridB, 128>>>(graph);

    combine_kernel<<<OUTSZ / (256 * 4), 256>>>(out);
    (void)in_sizes; (void)n_in; (void)out_size;
}

// round 5
// speedup vs baseline: 4.5204x; 1.4382x over previous
#include <cuda_runtime.h>
#include <cuda_bf16.h>
#include <math.h>

#define Bq 2
#define Nq 2048
#define Fq 128
#define Mq 8
#define Uq 64
#define NM (Nq * Mq)            // 16384 rows of A'
#define OUTSZ (Bq * Nq * Mq * Uq)

#define JSPLIT 2
#define JLEN (Nq / JSPLIT)      // 1024
#define JC 32                   // j per stage
#define NSTAGE (JLEN / JC)      // 32

// smem (bytes) for main kernel: A' 128 rows x 32 j bf16 (row stride 80B), hi+lo
#define SA 80
#define AH_OFF 0
#define AL_OFF (AH_OFF + 128 * SA)      // 10240
#define BH_OFF (AL_OFF + 128 * SA)      // 20480  (B: 64 u x 32 j bf16, stride 80)
#define BL_OFF (BH_OFF + 64 * SA)       // 25600
#define SMEM_MAIN (BL_OFF + 64 * SA)    // 30720

// device scratch (allocation-free rule)
__device__ float g_beta[Bq * Nq * Uq];
__device__ float g_alpha[OUTSZ];
__device__ float g_part[JSPLIT * OUTSZ];
__device__ unsigned short g_bTh[Bq * Uq * Nq];   // betaT hi bf16 [b][u][n]
__device__ unsigned short g_bTl[Bq * Uq * Nq];   // betaT lo bf16

__device__ __forceinline__ unsigned smem_u32(const void* p) {
    unsigned r;
    asm("{ .reg .u64 t; cvta.to.shared.u64 t, %1; cvt.u32.u64 %0, t; }"
        : "=r"(r) : "l"(p));
    return r;
}
__device__ __forceinline__ unsigned cvt_bf16x2(float lo_elem, float hi_elem) {
    unsigned r;   // low 16 bits <- lo_elem, high <- hi_elem
    asm("cvt.rn.bf16x2.f32 %0, %1, %2;" : "=r"(r) : "f"(hi_elem), "f"(lo_elem));
    return r;
}
__device__ __forceinline__ float bf_lo_f(unsigned h) { return __uint_as_float(h << 16); }
__device__ __forceinline__ float bf_hi_f(unsigned h) { return __uint_as_float(h & 0xffff0000u); }

#define LDSM4(r0, r1, r2, r3, addr) \
    asm volatile("ldmatrix.sync.aligned.m8n8.x4.shared.b16 {%0,%1,%2,%3}, [%4];" \
                 : "=r"(r0), "=r"(r1), "=r"(r2), "=r"(r3) : "r"(addr))

__device__ __forceinline__ void mma_bf16(float* c, const unsigned* a, const unsigned* b) {
    asm volatile(
        "mma.sync.aligned.m16n8k16.row.col.f32.bf16.bf16.f32 "
        "{%0,%1,%2,%3}, {%4,%5,%6,%7}, {%8,%9}, {%0,%1,%2,%3};"
        : "+f"(c[0]), "+f"(c[1]), "+f"(c[2]), "+f"(c[3])
        : "r"(a[0]), "r"(a[1]), "r"(a[2]), "r"(a[3]), "r"(b[0]), "r"(b[1]));
}

// ---------------------------------------------------------------------------
// Kernel A: beta = seq @ e_w, alpha = seq @ v_w.
// 64-row block tile now (grid 9 x 64) for occupancy.
// ---------------------------------------------------------------------------
__global__ void __launch_bounds__(256) precompute_kernel(
        const float* __restrict__ seq,
        const float* __restrict__ e_w,
        const float* __restrict__ v_w) {
    __shared__ float sS[64][33];
    __shared__ float sW[32][68];

    const int bx = blockIdx.x;
    const int by = blockIdx.y;
    const int row0 = by * 64;

    const float* wsrc;
    int wstride, c0;
    if (bx == 0) { wsrc = e_w; wstride = Uq;      c0 = 0; }
    else         { wsrc = v_w; wstride = Mq * Uq; c0 = (bx - 1) * 64; }

    const int tid = threadIdx.x;
    const int tx = tid & 15;
    const int ty = tid >> 4;

    float acc[4][4];
#pragma unroll
    for (int r = 0; r < 4; r++)
#pragma unroll
        for (int c = 0; c < 4; c++) acc[r][c] = 0.f;

    for (int fb = 0; fb < Fq; fb += 32) {
#pragma unroll
        for (int k = 0; k < 2; k++) {
            int v = tid + k * 256;       // < 512
            int r = v >> 3, fq = (v & 7) * 4;
            float4 t = *(const float4*)&seq[(row0 + r) * Fq + fb + fq];
            sS[r][fq + 0] = t.x; sS[r][fq + 1] = t.y;
            sS[r][fq + 2] = t.z; sS[r][fq + 3] = t.w;
        }
#pragma unroll
        for (int k = 0; k < 2; k++) {
            int v = tid + k * 256;       // < 512
            int f = v >> 4, cq = (v & 15) * 4;
            float4 t = *(const float4*)&wsrc[(fb + f) * wstride + c0 + cq];
            *(float4*)&sW[f][cq] = t;
        }
        __syncthreads();

#pragma unroll 4
        for (int f = 0; f < 32; f++) {
            float a[4];
#pragma unroll
            for (int r = 0; r < 4; r++) a[r] = sS[ty * 4 + r][f];
            float4 b4 = *(const float4*)&sW[f][tx * 4];
            float bb[4] = {b4.x, b4.y, b4.z, b4.w};
#pragma unroll
            for (int r = 0; r < 4; r++)
#pragma unroll
                for (int c = 0; c < 4; c++)
                    acc[r][c] = fmaf(a[r], bb[c], acc[r][c]);
        }
        __syncthreads();
    }

#pragma unroll
    for (int r = 0; r < 4; r++) {
        const int bn = row0 + ty * 4 + r;
#pragma unroll
        for (int c = 0; c < 4; c++) {
            const int col = tx * 4 + c;
            if (bx == 0) g_beta[bn * Uq + col] = acc[r][c];
            else         g_alpha[bn * (Mq * Uq) + c0 + col] = acc[r][c];
        }
    }
}

// ---------------------------------------------------------------------------
// Kernel T: betaT hi/lo bf16: g_bT*[b][u][n] from g_beta[b][n][u].
// ---------------------------------------------------------------------------
__global__ void __launch_bounds__(256) betaT_kernel() {
    __shared__ float s[128][65];
    const int b  = blockIdx.y;
    const int n0 = blockIdx.x * 128;
    const int tid = threadIdx.x;

#pragma unroll
    for (int k = 0; k < 8; k++) {
        int v = tid + k * 256;          // < 2048 float4
        int n = v >> 4, uq = (v & 15) * 4;
        float4 t = *(const float4*)&g_beta[((b * Nq) + n0 + n) * Uq + uq];
        s[n][uq + 0] = t.x; s[n][uq + 1] = t.y;
        s[n][uq + 2] = t.z; s[n][uq + 3] = t.w;
    }
    __syncthreads();

    const int w = tid >> 5, l = tid & 31;
#pragma unroll
    for (int r = 0; r < 8; r++) {
        int u = w * 8 + r;
        float a0 = s[4 * l + 0][u], a1 = s[4 * l + 1][u];
        float a2 = s[4 * l + 2][u], a3 = s[4 * l + 3][u];
        unsigned h01 = cvt_bf16x2(a0, a1), h23 = cvt_bf16x2(a2, a3);
        float r0 = a0 - bf_lo_f(h01), r1 = a1 - bf_hi_f(h01);
        float r2 = a2 - bf_lo_f(h23), r3 = a3 - bf_hi_f(h23);
        unsigned l01 = cvt_bf16x2(r0, r1), l23 = cvt_bf16x2(r2, r3);
        size_t idx = (size_t)(b * Uq + u) * Nq + n0 + 4 * l;
        *(uint2*)&g_bTh[idx] = make_uint2(h01, h23);
        *(uint2*)&g_bTl[idx] = make_uint2(l01, l23);
    }
}

// ---------------------------------------------------------------------------
// Kernel B (main): C[(i*8+m), u] = sum_j graph[b,i,j,m] * beta[b,j,u]
// via mma.sync m16n8k16 bf16, 3-pass split precision (hi/lo).
// Grid: x = 128 row-tiles (128 rows = 16 i x 8 m), y = (b<<1)|js. 256 threads.
// Warp (8): wr=w>>1 row-group (32 rows), wc=w&1 col-group (32 u).
// ---------------------------------------------------------------------------
__global__ void __launch_bounds__(256, 2) multigraph_mma_kernel(
        const float* __restrict__ graph) {
    __shared__ __align__(16) char smem[SMEM_MAIN];
    const unsigned sb = smem_u32(smem);

    const int tid = threadIdx.x;
    const int l = tid & 31;
    const int w = tid >> 5;
    const int wr = w >> 1;
    const int wc = w & 1;

    const int rt0 = blockIdx.x * 128;        // global A' row base
    const int b   = blockIdx.y >> 1;
    const int js  = blockIdx.y & 1;
    const int i0  = rt0 >> 3;                // graph i base (multiple of 16)
    const int jbase = js * JLEN;

    float acc[2][4][4];
#pragma unroll
    for (int rt = 0; rt < 2; rt++)
#pragma unroll
        for (int nt = 0; nt < 4; nt++)
#pragma unroll
            for (int k = 0; k < 4; k++) acc[rt][nt][k] = 0.f;

    // ldmatrix addresses (constant across stages)
    // A: row = wr*32 + rt*16 + (l&15), k byte = ks*32 + (l>>4)*16
    const unsigned aRow = (unsigned)(wr * 32 + (l & 15)) * SA + ((l >> 4) * 16);
    // B: row = wc*32 + p*16 + (l&7) + ((l>>4)&1)*8, k byte = ks*32 + ((l>>3)&1)*16
    const unsigned bRow = (unsigned)(wc * 32 + (l & 7) + ((l >> 4) & 1) * 8) * SA
                        + (((l >> 3) & 1) * 16);

    const size_t bT_base = (size_t)b * Uq * Nq;

#pragma unroll 1
    for (int s = 0; s < NSTAGE; s++) {
        const int j0 = jbase + s * JC;

        // ---- stage A': 128 rows x 32 j, hi/lo bf16. 2 cells per thread.
#pragma unroll
        for (int a = 0; a < 2; a++) {
            int cell = tid + a * 256;            // < 512
            int row = cell & 127;                // (i_local*8 + m)
            int joct = cell >> 7;                // 0..3
            int il = row >> 3, m = row & 7;
            const float* gp = graph
                + (((size_t)(b * Nq) + i0 + il) * Nq + j0 + joct * 8) * Mq + m;
            float v[8];
#pragma unroll
            for (int jj = 0; jj < 8; jj++) v[jj] = gp[jj * Mq];
            unsigned h[4], lo[4];
#pragma unroll
            for (int k = 0; k < 4; k++) {
                h[k] = cvt_bf16x2(v[2 * k], v[2 * k + 1]);
                float r0 = v[2 * k]     - bf_lo_f(h[k]);
                float r1 = v[2 * k + 1] - bf_hi_f(h[k]);
                lo[k] = cvt_bf16x2(r0, r1);
            }
            unsigned off = (unsigned)row * SA + joct * 16;
            *(uint4*)(smem + AH_OFF + off) = make_uint4(h[0], h[1], h[2], h[3]);
            *(uint4*)(smem + AL_OFF + off) = make_uint4(lo[0], lo[1], lo[2], lo[3]);
        }
        // ---- stage B: 64 u x 32 j hi/lo
        {
            int u = tid >> 2, jq = tid & 3;
            size_t src = bT_base + (size_t)u * Nq + j0 + jq * 8;
            unsigned off = (unsigned)u * SA + jq * 16;
            *(uint4*)(smem + BH_OFF + off) = *(const uint4*)&g_bTh[src];
            *(uint4*)(smem + BL_OFF + off) = *(const uint4*)&g_bTl[src];
        }
        __syncthreads();

        // ---- mma: 2 k16 steps x 3 passes
#pragma unroll
        for (int ks = 0; ks < 2; ks++) {
            unsigned ah[2][4], al[2][4], bh[8], bl[8];
#pragma unroll
            for (int rt = 0; rt < 2; rt++) {
                unsigned aoff = aRow + (unsigned)rt * 16 * SA + ks * 32;
                LDSM4(ah[rt][0], ah[rt][1], ah[rt][2], ah[rt][3],
                      sb + AH_OFF + aoff);
                LDSM4(al[rt][0], al[rt][1], al[rt][2], al[rt][3],
                      sb + AL_OFF + aoff);
            }
#pragma unroll
            for (int p = 0; p < 2; p++) {
                unsigned boff = bRow + (unsigned)p * 16 * SA + ks * 32;
                LDSM4(bh[p * 4 + 0], bh[p * 4 + 1], bh[p * 4 + 2], bh[p * 4 + 3],
                      sb + BH_OFF + boff);
                LDSM4(bl[p * 4 + 0], bl[p * 4 + 1], bl[p * 4 + 2], bl[p * 4 + 3],
                      sb + BL_OFF + boff);
            }
#pragma unroll
            for (int rt = 0; rt < 2; rt++)
#pragma unroll
                for (int nt = 0; nt < 4; nt++) {
                    const unsigned* bhf = &bh[nt * 2];   // {k0-7, k8-15}
                    const unsigned* blf = &bl[nt * 2];
                    mma_bf16(acc[rt][nt], ah[rt], bhf);
                    mma_bf16(acc[rt][nt], al[rt], bhf);
                    mma_bf16(acc[rt][nt], ah[rt], blf);
                }
        }
        __syncthreads();
    }

    // epilogue: write fp32 partials. C frag: rows (l>>2), (l>>2)+8; cols 2*(l&3).
    float* part = g_part + (size_t)js * OUTSZ + (size_t)b * NM * Uq;
#pragma unroll
    for (int rt = 0; rt < 2; rt++) {
        const int r0 = rt0 + wr * 32 + rt * 16 + (l >> 2);
#pragma unroll
        for (int nt = 0; nt < 4; nt++) {
            const int u = wc * 32 + nt * 8 + (l & 3) * 2;
            float2 o0 = make_float2(acc[rt][nt][0], acc[rt][nt][1]);
            float2 o1 = make_float2(acc[rt][nt][2], acc[rt][nt][3]);
            *(float2*)&part[(size_t)r0 * Uq + u] = o0;
            *(float2*)&part[(size_t)(r0 + 8) * Uq + u] = o1;
        }
    }
}

// ---------------------------------------------------------------------------
// Kernel C: out = sigmoid(part0 + part1 + alpha)
// ---------------------------------------------------------------------------
__global__ void __launch_bounds__(256) combine_kernel(float* __restrict__ out) {
    const long long idx = ((long long)blockIdx.x * 256 + threadIdx.x) * 4;
    float4 s = *(const float4*)&g_alpha[idx];
#pragma unroll
    for (int p = 0; p < JSPLIT; p++) {
        float4 t = *(const float4*)&g_part[(long long)p * OUTSZ + idx];
        s.x += t.x; s.y += t.y; s.z += t.z; s.w += t.w;
    }
    float4 o;
    o.x = 1.0f / (1.0f + __expf(-s.x));
    o.y = 1.0f / (1.0f + __expf(-s.y));
    o.z = 1.0f / (1.0f + __expf(-s.z));
    o.w = 1.0f / (1.0f + __expf(-s.w));
    *(float4*)&out[idx] = o;
}

// ---------------------------------------------------------------------------
extern "C" void kernel_launch(void* const* d_in, const int* in_sizes, int n_in,
                              void* d_out, int out_size) {
    const float* seq   = (const float*)d_in[0];   // (B,N,F)
    const float* graph = (const float*)d_in[1];   // (B,N,N,M)
    const float* e_w   = (const float*)d_in[2];   // (F,U)
    const float* v_w   = (const float*)d_in[3];   // (F,M,U)
    float* out = (float*)d_out;                   // (B,N,M,U)

    dim3 gridA(9, 64);
    precompute_kernel<<<gridA, 256>>>(seq, e_w, v_w);

    dim3 gridT(16, 2);
    betaT_kernel<<<gridT, 256>>>();

    dim3 gridB(128, Bq * JSPLIT);
    multigraph_mma_kernel<<<gridB, 256>>>(graph);

    combine_kernel<<<OUTSZ / (256 * 4), 256>>>(out);
    (void)in_sizes; (void)n_in; (void)out_size;
}